// round 1
// baseline (speedup 1.0000x reference)
#include <cuda_runtime.h>

// ---------------------------------------------------------------------------
// GroupedQueryAttention baseline, fp32:
//   1. Q = x@Wq+bq, K = x@Wk+bk, V = x@Wv+bv      (tiled SGEMM)
//   2. flash attention per (b, h, q-tile)          (online softmax)
//   3. out = ctx@Wo+bo                             (tiled SGEMM)
// ---------------------------------------------------------------------------

#define D_MODEL 2048
#define KV_DIM  512
#define BATCH   4
#define S_LEN   1024
#define NTOK    (BATCH * S_LEN)   // 4096
#define HEADS   32
#define KVH     8
#define HD      64

// Scratch (device globals: no allocation allowed in kernel_launch)
__device__ float g_q[NTOK * (size_t)D_MODEL];   // [token][h*64+d]
__device__ float g_k[NTOK * (size_t)KV_DIM];    // [token][hk*64+d]
__device__ float g_v[NTOK * (size_t)KV_DIM];
__device__ float g_ctx[NTOK * (size_t)D_MODEL];

// ---------------------------------------------------------------------------
// SGEMM: C[M,N] = A[M,K] @ W[K,N] + bias[N]
// Block tile 128x128, K-step 8, 256 threads, 8x8 register tile per thread.
// ---------------------------------------------------------------------------
template <int N, int K>
__device__ __forceinline__ void sgemm_body(const float* __restrict__ A,
                                           const float* __restrict__ W,
                                           const float* __restrict__ bias,
                                           float* __restrict__ C)
{
    __shared__ float As[8][128];   // transposed A tile: As[k][row]
    __shared__ float Bs[8][128];   // Bs[k][col]

    const int tid = threadIdx.x;
    const int tx = tid & 15;       // 0..15 -> output cols tx*8..tx*8+7
    const int ty = tid >> 4;       // 0..15 -> output rows ty*8..ty*8+7
    const int row0 = blockIdx.y * 128;
    const int col0 = blockIdx.x * 128;

    // load indices
    const int arow = tid >> 1;           // 0..127
    const int acol = (tid & 1) << 2;     // 0 or 4
    const int brow = tid >> 5;           // 0..7
    const int bcol = (tid & 31) << 2;    // 0..124

    float acc[8][8];
#pragma unroll
    for (int i = 0; i < 8; i++)
#pragma unroll
        for (int j = 0; j < 8; j++) acc[i][j] = 0.f;

    const float* Aptr = A + (size_t)(row0 + arow) * K + acol;
    const float* Wptr = W + (size_t)brow * N + col0 + bcol;

    for (int k0 = 0; k0 < K; k0 += 8) {
        float4 av = *(const float4*)(Aptr + k0);
        float4 bv = *(const float4*)(Wptr + (size_t)k0 * N);
        __syncthreads();
        As[acol + 0][arow] = av.x;
        As[acol + 1][arow] = av.y;
        As[acol + 2][arow] = av.z;
        As[acol + 3][arow] = av.w;
        *(float4*)(&Bs[brow][bcol]) = bv;
        __syncthreads();
#pragma unroll
        for (int kk = 0; kk < 8; kk++) {
            float a[8], b[8];
            *(float4*)(a)     = *(const float4*)(&As[kk][ty * 8]);
            *(float4*)(a + 4) = *(const float4*)(&As[kk][ty * 8 + 4]);
            *(float4*)(b)     = *(const float4*)(&Bs[kk][tx * 8]);
            *(float4*)(b + 4) = *(const float4*)(&Bs[kk][tx * 8 + 4]);
#pragma unroll
            for (int i = 0; i < 8; i++)
#pragma unroll
                for (int j = 0; j < 8; j++)
                    acc[i][j] = fmaf(a[i], b[j], acc[i][j]);
        }
    }

#pragma unroll
    for (int i = 0; i < 8; i++) {
        const int r = row0 + ty * 8 + i;
        float* crow = C + (size_t)r * N + col0 + tx * 8;
        const float* bptr = bias + col0 + tx * 8;
#pragma unroll
        for (int j4 = 0; j4 < 8; j4 += 4) {
            float4 o;
            o.x = acc[i][j4 + 0] + bptr[j4 + 0];
            o.y = acc[i][j4 + 1] + bptr[j4 + 1];
            o.z = acc[i][j4 + 2] + bptr[j4 + 2];
            o.w = acc[i][j4 + 3] + bptr[j4 + 3];
            *(float4*)(crow + j4) = o;
        }
    }
}

__global__ __launch_bounds__(256) void proj_q_kernel(const float* __restrict__ x,
                                                     const float* __restrict__ W,
                                                     const float* __restrict__ b)
{
    sgemm_body<D_MODEL, D_MODEL>(x, W, b, g_q);
}

__global__ __launch_bounds__(256) void proj_k_kernel(const float* __restrict__ x,
                                                     const float* __restrict__ W,
                                                     const float* __restrict__ b)
{
    sgemm_body<KV_DIM, D_MODEL>(x, W, b, g_k);
}

__global__ __launch_bounds__(256) void proj_v_kernel(const float* __restrict__ x,
                                                     const float* __restrict__ W,
                                                     const float* __restrict__ b)
{
    sgemm_body<KV_DIM, D_MODEL>(x, W, b, g_v);
}

__global__ __launch_bounds__(256) void proj_o_kernel(const float* __restrict__ W,
                                                     const float* __restrict__ b,
                                                     float* __restrict__ out)
{
    sgemm_body<D_MODEL, D_MODEL>(g_ctx, W, b, out);
}

// ---------------------------------------------------------------------------
// Flash attention, fp32. Grid: (S/64 q-tiles, B*H). 256 threads.
// Shared: Qs[64][64] | KP[64][65] (K tile, then reused for P) | Vs[64][64]
// Thread (tx,ty): owns q-rows ty*4..ty*4+3 and score/ctx cols tx*4..tx*4+3.
// Row reductions via width-16 shuffles (a row's 16 owners sit in one
// half-warp: lanes [0,16) for even ty, [16,32) for odd ty).
// ---------------------------------------------------------------------------
#define SMEM_ATT ((64 * 64 + 64 * 65 + 64 * 64) * 4)   // 49408 bytes

__global__ __launch_bounds__(256) void attention_kernel()
{
    extern __shared__ float sm[];
    float* Qs = sm;               // 64*64
    float* KP = sm + 64 * 64;     // 64*65 (padded: K reads are column-of-row)
    float* Vs = KP + 64 * 65;     // 64*64

    const int bh = blockIdx.y;
    const int b  = bh >> 5;
    const int h  = bh & 31;
    const int hk = h >> 2;        // repeat_interleave: kv head = h / 4
    const int q0 = blockIdx.x * 64;

    const int tid = threadIdx.x;
    const int tx = tid & 15;
    const int ty = tid >> 4;

    const float* qptr  = g_q + (size_t)(b * S_LEN + q0) * D_MODEL + h * HD;
    const float* kbase = g_k + (size_t)b * S_LEN * KV_DIM + hk * HD;
    const float* vbase = g_v + (size_t)b * S_LEN * KV_DIM + hk * HD;

    // Load Q tile, folding the 1/sqrt(d) = 0.125 scale into Q.
    for (int idx = tid; idx < 64 * 16; idx += 256) {
        const int r = idx >> 4, c4 = (idx & 15) << 2;
        float4 val = *(const float4*)(qptr + (size_t)r * D_MODEL + c4);
        val.x *= 0.125f; val.y *= 0.125f; val.z *= 0.125f; val.w *= 0.125f;
        *(float4*)(Qs + r * 64 + c4) = val;
    }

    float m_i[4], l_i[4], acc[4][4];
#pragma unroll
    for (int i = 0; i < 4; i++) {
        m_i[i] = -1e30f;
        l_i[i] = 0.f;
#pragma unroll
        for (int j = 0; j < 4; j++) acc[i][j] = 0.f;
    }

    for (int kt = 0; kt < S_LEN / 64; kt++) {
        __syncthreads();   // prev iter's P@V reads of KP done; Q load done (iter 0)
        const float* kp = kbase + (size_t)(kt * 64) * KV_DIM;
        const float* vp = vbase + (size_t)(kt * 64) * KV_DIM;
        for (int idx = tid; idx < 64 * 16; idx += 256) {
            const int r = idx >> 4, c4 = (idx & 15) << 2;
            float4 kv = *(const float4*)(kp + (size_t)r * KV_DIM + c4);
            KP[r * 65 + c4 + 0] = kv.x;
            KP[r * 65 + c4 + 1] = kv.y;
            KP[r * 65 + c4 + 2] = kv.z;
            KP[r * 65 + c4 + 3] = kv.w;
            *(float4*)(Vs + r * 64 + c4) = *(const float4*)(vp + (size_t)r * KV_DIM + c4);
        }
        __syncthreads();

        // S = (Q/8) @ K^T : s[i][j] for rows ty*4+i, cols tx*4+j
        float s[4][4];
#pragma unroll
        for (int i = 0; i < 4; i++)
#pragma unroll
            for (int j = 0; j < 4; j++) s[i][j] = 0.f;

        for (int kk = 0; kk < 64; kk++) {
            float a[4], bb[4];
#pragma unroll
            for (int i = 0; i < 4; i++) a[i] = Qs[(ty * 4 + i) * 64 + kk];
#pragma unroll
            for (int j = 0; j < 4; j++) bb[j] = KP[(tx * 4 + j) * 65 + kk];
#pragma unroll
            for (int i = 0; i < 4; i++)
#pragma unroll
                for (int j = 0; j < 4; j++)
                    s[i][j] = fmaf(a[i], bb[j], s[i][j]);
        }
        __syncthreads();   // everyone done reading K before P overwrites KP

        // Online softmax update + write P into KP
#pragma unroll
        for (int i = 0; i < 4; i++) {
            float mx = fmaxf(fmaxf(s[i][0], s[i][1]), fmaxf(s[i][2], s[i][3]));
#pragma unroll
            for (int off = 8; off >= 1; off >>= 1)
                mx = fmaxf(mx, __shfl_xor_sync(0xffffffffu, mx, off, 16));
            const float m_new = fmaxf(m_i[i], mx);
            const float corr = __expf(m_i[i] - m_new);
            float rsum = 0.f;
#pragma unroll
            for (int j = 0; j < 4; j++) {
                s[i][j] = __expf(s[i][j] - m_new);
                rsum += s[i][j];
            }
#pragma unroll
            for (int off = 8; off >= 1; off >>= 1)
                rsum += __shfl_xor_sync(0xffffffffu, rsum, off, 16);
            l_i[i] = l_i[i] * corr + rsum;
            m_i[i] = m_new;
#pragma unroll
            for (int j = 0; j < 4; j++) acc[i][j] *= corr;
#pragma unroll
            for (int j = 0; j < 4; j++)
                KP[(ty * 4 + i) * 65 + tx * 4 + j] = s[i][j];
        }
        __syncthreads();

        // ctx += P @ V
        for (int kk = 0; kk < 64; kk++) {
            float p[4], vv[4];
#pragma unroll
            for (int i = 0; i < 4; i++) p[i] = KP[(ty * 4 + i) * 65 + kk];
#pragma unroll
            for (int j = 0; j < 4; j++) vv[j] = Vs[kk * 64 + tx * 4 + j];
#pragma unroll
            for (int i = 0; i < 4; i++)
#pragma unroll
                for (int j = 0; j < 4; j++)
                    acc[i][j] = fmaf(p[i], vv[j], acc[i][j]);
        }
    }

    // Normalize and write ctx in [token][h*64+d] layout (ready for O proj)
    float* optr = g_ctx + (size_t)(b * S_LEN + q0) * D_MODEL + h * HD;
#pragma unroll
    for (int i = 0; i < 4; i++) {
        const float inv = 1.f / l_i[i];
        float4 o;
        o.x = acc[i][0] * inv;
        o.y = acc[i][1] * inv;
        o.z = acc[i][2] * inv;
        o.w = acc[i][3] * inv;
        *(float4*)(optr + (size_t)(ty * 4 + i) * D_MODEL + tx * 4) = o;
    }
}

// ---------------------------------------------------------------------------
extern "C" void kernel_launch(void* const* d_in, const int* in_sizes, int n_in,
                              void* d_out, int out_size)
{
    const float* x  = (const float*)d_in[0];
    const float* Wq = (const float*)d_in[1];
    const float* bq = (const float*)d_in[2];
    const float* Wk = (const float*)d_in[3];
    const float* bk = (const float*)d_in[4];
    const float* Wv = (const float*)d_in[5];
    const float* bv = (const float*)d_in[6];
    const float* Wo = (const float*)d_in[7];
    const float* bo = (const float*)d_in[8];
    float* out = (float*)d_out;

    cudaFuncSetAttribute(attention_kernel,
                         cudaFuncAttributeMaxDynamicSharedMemorySize, SMEM_ATT);

    proj_q_kernel<<<dim3(D_MODEL / 128, NTOK / 128), 256>>>(x, Wq, bq);
    proj_k_kernel<<<dim3(KV_DIM / 128, NTOK / 128), 256>>>(x, Wk, bk);
    proj_v_kernel<<<dim3(KV_DIM / 128, NTOK / 128), 256>>>(x, Wv, bv);
    attention_kernel<<<dim3(S_LEN / 64, BATCH * HEADS), 256, SMEM_ATT>>>();
    proj_o_kernel<<<dim3(D_MODEL / 128, NTOK / 128), 256>>>(Wo, bo, out);
}

// round 4
// speedup vs baseline: 1.7993x; 1.7993x over previous
#include <cuda_runtime.h>
#include <cuda_bf16.h>
#include <cstdint>

#define D_MODEL 2048
#define KV_DIM  512
#define BATCH   4
#define S_LEN   1024
#define NTOK    4096
#define HEADS   32
#define HD      64
#define KTOT    2048          // inner dim of every projection GEMM

// ---------------------------------------------------------------------------
// Device-global scratch (no allocations allowed)
// ---------------------------------------------------------------------------
__device__ __align__(256) float g_q[NTOK * (size_t)D_MODEL];
__device__ __align__(256) float g_k[NTOK * (size_t)KV_DIM];
__device__ __align__(256) float g_v[NTOK * (size_t)KV_DIM];
__device__ __align__(256) float g_ctx[NTOK * (size_t)D_MODEL];

// bf16 split activations (x first, reused for ctx before O-proj)
__device__ __align__(256) __nv_bfloat16 g_ah[NTOK * (size_t)KTOT];
__device__ __align__(256) __nv_bfloat16 g_al[NTOK * (size_t)KTOT];
// transposed weights [N][K] bf16 hi/lo
__device__ __align__(256) __nv_bfloat16 g_wqh[D_MODEL * (size_t)KTOT];
__device__ __align__(256) __nv_bfloat16 g_wql[D_MODEL * (size_t)KTOT];
__device__ __align__(256) __nv_bfloat16 g_wkh[KV_DIM * (size_t)KTOT];
__device__ __align__(256) __nv_bfloat16 g_wkl[KV_DIM * (size_t)KTOT];
__device__ __align__(256) __nv_bfloat16 g_wvh[KV_DIM * (size_t)KTOT];
__device__ __align__(256) __nv_bfloat16 g_wvl[KV_DIM * (size_t)KTOT];
__device__ __align__(256) __nv_bfloat16 g_woh[D_MODEL * (size_t)KTOT];
__device__ __align__(256) __nv_bfloat16 g_wol[D_MODEL * (size_t)KTOT];

// ---------------------------------------------------------------------------
// Helpers
// ---------------------------------------------------------------------------
__device__ __forceinline__ uint32_t smem_u32(const void* p) {
    uint32_t a;
    asm("{ .reg .u64 t; cvta.to.shared.u64 t, %1; cvt.u32.u64 %0, t; }"
        : "=r"(a) : "l"(p));
    return a;
}
__device__ __forceinline__ void ldmx4(uint32_t* r, uint32_t addr) {
    asm volatile("ldmatrix.sync.aligned.m8n8.x4.shared.b16 {%0,%1,%2,%3}, [%4];"
                 : "=r"(r[0]), "=r"(r[1]), "=r"(r[2]), "=r"(r[3]) : "r"(addr));
}
__device__ __forceinline__ void mma16816(float* c, const uint32_t* a,
                                         const uint32_t* b) {
    asm volatile(
        "mma.sync.aligned.m16n8k16.row.col.f32.bf16.bf16.f32 "
        "{%0,%1,%2,%3}, {%4,%5,%6,%7}, {%8,%9}, {%0,%1,%2,%3};"
        : "+f"(c[0]), "+f"(c[1]), "+f"(c[2]), "+f"(c[3])
        : "r"(a[0]), "r"(a[1]), "r"(a[2]), "r"(a[3]), "r"(b[0]), "r"(b[1]));
}

// ---------------------------------------------------------------------------
// Preprocessing kernels: bf16 hi/lo split, and transpose+split for weights
// ---------------------------------------------------------------------------
__global__ __launch_bounds__(256) void split_kernel(const float* __restrict__ in,
                                                    __nv_bfloat16* __restrict__ hi,
                                                    __nv_bfloat16* __restrict__ lo,
                                                    int n4)
{
    int i = blockIdx.x * blockDim.x + threadIdx.x;
    if (i >= n4) return;
    float4 v = *(const float4*)(in + (size_t)i * 4);
    __nv_bfloat16 h0 = __float2bfloat16(v.x), h1 = __float2bfloat16(v.y);
    __nv_bfloat16 h2 = __float2bfloat16(v.z), h3 = __float2bfloat16(v.w);
    __nv_bfloat16 l0 = __float2bfloat16(v.x - __bfloat162float(h0));
    __nv_bfloat16 l1 = __float2bfloat16(v.y - __bfloat162float(h1));
    __nv_bfloat16 l2 = __float2bfloat16(v.z - __bfloat162float(h2));
    __nv_bfloat16 l3 = __float2bfloat16(v.w - __bfloat162float(h3));
    __nv_bfloat162* H = (__nv_bfloat162*)(hi + (size_t)i * 4);
    __nv_bfloat162* L = (__nv_bfloat162*)(lo + (size_t)i * 4);
    H[0] = __nv_bfloat162(h0, h1); H[1] = __nv_bfloat162(h2, h3);
    L[0] = __nv_bfloat162(l0, l1); L[1] = __nv_bfloat162(l2, l3);
}

// W[K][N] fp32 -> out[N][K] bf16 hi/lo
__global__ __launch_bounds__(256) void transpose_split_kernel(
    const float* __restrict__ W,
    __nv_bfloat16* __restrict__ th, __nv_bfloat16* __restrict__ tl,
    int K, int N)
{
    __shared__ float t[32][33];
    const int n0 = blockIdx.x * 32, k0 = blockIdx.y * 32;
    const int tx = threadIdx.x, ty = threadIdx.y;   // (32, 8)
#pragma unroll
    for (int j = 0; j < 4; j++)
        t[ty + 8 * j][tx] = W[(size_t)(k0 + ty + 8 * j) * N + n0 + tx];
    __syncthreads();
#pragma unroll
    for (int j = 0; j < 4; j++) {
        float v = t[tx][ty + 8 * j];
        __nv_bfloat16 h = __float2bfloat16(v);
        __nv_bfloat16 l = __float2bfloat16(v - __bfloat162float(h));
        size_t o = (size_t)(n0 + ty + 8 * j) * K + k0 + tx;
        th[o] = h;
        tl[o] = l;
    }
}

// ---------------------------------------------------------------------------
// mma.sync bf16-split GEMM: C[M,Ntot] = (Ah+Al) @ (Bh+Bl)^T + bias
// CTA 128x128, BK=32, 256 thr (8 warps, 2x4), warp tile 64x32,
// double-buffered cp.async, ldmatrix fragments, fp32 register accum.
// smem rows padded to 80B -> conflict-free ldmatrix (all 32 banks hit once).
// ---------------------------------------------------------------------------
#define BM 128
#define BN 128
#define BK 32
#define ROWB   80                  // 32 bf16 (64B) + 16B pad
#define MATB   (128 * ROWB)        // 10240 B per operand tile
#define STAGEB (4 * MATB)          // Ah | Al | Bh | Bl
#define NCHUNK (KTOT / BK)         // 64
#define SMEM_GEMM (2 * STAGEB)     // 81920 B

__global__ __launch_bounds__(256, 1)
void gemm_mma_kernel(const __nv_bfloat16* __restrict__ Ah,
                     const __nv_bfloat16* __restrict__ Al,
                     const __nv_bfloat16* __restrict__ Bh,
                     const __nv_bfloat16* __restrict__ Bl,
                     const float* __restrict__ bias,
                     float* __restrict__ C, int Ntot)
{
    extern __shared__ char smraw[];
    const uint32_t sb = smem_u32(smraw);
    const int tid  = threadIdx.x;
    const int wid  = tid >> 5, lane = tid & 31;
    const int warpM = wid & 1;          // 0..1 -> 64 rows each
    const int warpN = wid >> 1;         // 0..3 -> 32 cols each
    const int m0 = blockIdx.y * BM, n0 = blockIdx.x * BN;

    const __nv_bfloat16* src0 = Ah + (size_t)m0 * KTOT;
    const __nv_bfloat16* src1 = Al + (size_t)m0 * KTOT;
    const __nv_bfloat16* src2 = Bh + (size_t)n0 * KTOT;
    const __nv_bfloat16* src3 = Bl + (size_t)n0 * KTOT;

    // ---- async tile loader: 4 operands x 128 rows x 64B ----
    const int ldrow = tid >> 2;             // 0..63  (+64 on second pass)
    const int ldseg = (tid & 3) << 4;       // byte seg 0/16/32/48
    const int ldoff = (tid & 3) << 3;       // elem offset 0/8/16/24

#define LOAD_CHUNK(stage, c)                                                   \
    do {                                                                       \
        const uint32_t st_ = sb + (stage) * STAGEB;                            \
        const int k0_ = (c) * BK;                                              \
        const __nv_bfloat16* gs_[4] = {src0, src1, src2, src3};                \
        _Pragma("unroll")                                                      \
        for (int mat_ = 0; mat_ < 4; mat_++) {                                 \
            _Pragma("unroll")                                                  \
            for (int it_ = 0; it_ < 2; it_++) {                                \
                const int row_ = ldrow + it_ * 64;                             \
                const uint32_t dst_ = st_ + mat_ * MATB + row_ * ROWB + ldseg; \
                const void* g_ = gs_[mat_] + (size_t)row_ * KTOT + k0_ + ldoff;\
                asm volatile("cp.async.cg.shared.global [%0], [%1], 16;"       \
                             :: "r"(dst_), "l"(g_));                           \
            }                                                                  \
        }                                                                      \
        asm volatile("cp.async.commit_group;");                                \
    } while (0)

    float acc[4][4][4];
#pragma unroll
    for (int i = 0; i < 4; i++)
#pragma unroll
        for (int j = 0; j < 4; j++)
#pragma unroll
            for (int r = 0; r < 4; r++) acc[i][j][r] = 0.f;

    LOAD_CHUNK(0, 0);

    // ldmatrix per-lane address components
    const int rowA = lane & 15;
    const int offA = (lane >> 4) << 4;                       // 0 / 16
    const int rowB = (lane & 7) | ((lane >> 4) << 3);        // n row within 16
    const int offB = ((lane >> 3) & 1) << 4;                 // 0 / 16

    for (int c = 0; c < NCHUNK; c++) {
        if (c + 1 < NCHUNK) {
            LOAD_CHUNK((c + 1) & 1, c + 1);
            asm volatile("cp.async.wait_group 1;");
        } else {
            asm volatile("cp.async.wait_group 0;");
        }
        __syncthreads();

        const uint32_t base = sb + (c & 1) * STAGEB;
#pragma unroll
        for (int k16 = 0; k16 < 2; k16++) {
            const int kb = k16 * 32;
            uint32_t ah[4][4], al[4][4], bh[4][2], bl[4][2];
#pragma unroll
            for (int ms = 0; ms < 4; ms++) {
                const uint32_t ra = (warpM * 64 + ms * 16 + rowA) * ROWB + offA + kb;
                ldmx4(ah[ms], base + ra);
                ldmx4(al[ms], base + MATB + ra);
            }
#pragma unroll
            for (int p = 0; p < 2; p++) {
                const uint32_t rb = (warpN * 32 + p * 16 + rowB) * ROWB + offB + kb;
                uint32_t t[4];
                ldmx4(t, base + 2 * MATB + rb);
                bh[2 * p][0] = t[0]; bh[2 * p][1] = t[1];
                bh[2 * p + 1][0] = t[2]; bh[2 * p + 1][1] = t[3];
                ldmx4(t, base + 3 * MATB + rb);
                bl[2 * p][0] = t[0]; bl[2 * p][1] = t[1];
                bl[2 * p + 1][0] = t[2]; bl[2 * p + 1][1] = t[3];
            }
#pragma unroll
            for (int ms = 0; ms < 4; ms++)
#pragma unroll
                for (int ns = 0; ns < 4; ns++) {
                    mma16816(acc[ms][ns], ah[ms], bh[ns]);
                    mma16816(acc[ms][ns], ah[ms], bl[ns]);
                    mma16816(acc[ms][ns], al[ms], bh[ns]);
                }
        }
        __syncthreads();
    }

    // ---- epilogue: write fp32 + bias ----
    const int g = lane >> 2, t4 = lane & 3;
#pragma unroll
    for (int ms = 0; ms < 4; ms++) {
        const int r0 = m0 + warpM * 64 + ms * 16 + g;
#pragma unroll
        for (int ns = 0; ns < 4; ns++) {
            const int col = n0 + warpN * 32 + ns * 8 + t4 * 2;
            const float bx = bias[col], by = bias[col + 1];
            float2 o0, o1;
            o0.x = acc[ms][ns][0] + bx; o0.y = acc[ms][ns][1] + by;
            o1.x = acc[ms][ns][2] + bx; o1.y = acc[ms][ns][3] + by;
            *(float2*)(C + (size_t)r0 * Ntot + col) = o0;
            *(float2*)(C + (size_t)(r0 + 8) * Ntot + col) = o1;
        }
    }
#undef LOAD_CHUNK
}

// ---------------------------------------------------------------------------
// Flash attention, fp32 (unchanged from R1)
// ---------------------------------------------------------------------------
#define SMEM_ATT ((64 * 64 + 64 * 65 + 64 * 64) * 4)

__global__ __launch_bounds__(256) void attention_kernel()
{
    extern __shared__ float sm[];
    float* Qs = sm;
    float* KP = sm + 64 * 64;
    float* Vs = KP + 64 * 65;

    const int bh = blockIdx.y;
    const int b  = bh >> 5;
    const int h  = bh & 31;
    const int hk = h >> 2;
    const int q0 = blockIdx.x * 64;

    const int tid = threadIdx.x;
    const int tx = tid & 15;
    const int ty = tid >> 4;

    const float* qptr  = g_q + (size_t)(b * S_LEN + q0) * D_MODEL + h * HD;
    const float* kbase = g_k + (size_t)b * S_LEN * KV_DIM + hk * HD;
    const float* vbase = g_v + (size_t)b * S_LEN * KV_DIM + hk * HD;

    for (int idx = tid; idx < 64 * 16; idx += 256) {
        const int r = idx >> 4, c4 = (idx & 15) << 2;
        float4 val = *(const float4*)(qptr + (size_t)r * D_MODEL + c4);
        val.x *= 0.125f; val.y *= 0.125f; val.z *= 0.125f; val.w *= 0.125f;
        *(float4*)(Qs + r * 64 + c4) = val;
    }

    float m_i[4], l_i[4], acc[4][4];
#pragma unroll
    for (int i = 0; i < 4; i++) {
        m_i[i] = -1e30f; l_i[i] = 0.f;
#pragma unroll
        for (int j = 0; j < 4; j++) acc[i][j] = 0.f;
    }

    for (int kt = 0; kt < S_LEN / 64; kt++) {
        __syncthreads();
        const float* kp = kbase + (size_t)(kt * 64) * KV_DIM;
        const float* vp = vbase + (size_t)(kt * 64) * KV_DIM;
        for (int idx = tid; idx < 64 * 16; idx += 256) {
            const int r = idx >> 4, c4 = (idx & 15) << 2;
            float4 kv = *(const float4*)(kp + (size_t)r * KV_DIM + c4);
            KP[r * 65 + c4 + 0] = kv.x;
            KP[r * 65 + c4 + 1] = kv.y;
            KP[r * 65 + c4 + 2] = kv.z;
            KP[r * 65 + c4 + 3] = kv.w;
            *(float4*)(Vs + r * 64 + c4) = *(const float4*)(vp + (size_t)r * KV_DIM + c4);
        }
        __syncthreads();

        float s[4][4];
#pragma unroll
        for (int i = 0; i < 4; i++)
#pragma unroll
            for (int j = 0; j < 4; j++) s[i][j] = 0.f;

        for (int kk = 0; kk < 64; kk++) {
            float a[4], bb[4];
#pragma unroll
            for (int i = 0; i < 4; i++) a[i] = Qs[(ty * 4 + i) * 64 + kk];
#pragma unroll
            for (int j = 0; j < 4; j++) bb[j] = KP[(tx * 4 + j) * 65 + kk];
#pragma unroll
            for (int i = 0; i < 4; i++)
#pragma unroll
                for (int j = 0; j < 4; j++)
                    s[i][j] = fmaf(a[i], bb[j], s[i][j]);
        }
        __syncthreads();

#pragma unroll
        for (int i = 0; i < 4; i++) {
            float mx = fmaxf(fmaxf(s[i][0], s[i][1]), fmaxf(s[i][2], s[i][3]));
#pragma unroll
            for (int off = 8; off >= 1; off >>= 1)
                mx = fmaxf(mx, __shfl_xor_sync(0xffffffffu, mx, off, 16));
            const float m_new = fmaxf(m_i[i], mx);
            const float corr = __expf(m_i[i] - m_new);
            float rsum = 0.f;
#pragma unroll
            for (int j = 0; j < 4; j++) {
                s[i][j] = __expf(s[i][j] - m_new);
                rsum += s[i][j];
            }
#pragma unroll
            for (int off = 8; off >= 1; off >>= 1)
                rsum += __shfl_xor_sync(0xffffffffu, rsum, off, 16);
            l_i[i] = l_i[i] * corr + rsum;
            m_i[i] = m_new;
#pragma unroll
            for (int j = 0; j < 4; j++) acc[i][j] *= corr;
#pragma unroll
            for (int j = 0; j < 4; j++)
                KP[(ty * 4 + i) * 65 + tx * 4 + j] = s[i][j];
        }
        __syncthreads();

        for (int kk = 0; kk < 64; kk++) {
            float p[4], vv[4];
#pragma unroll
            for (int i = 0; i < 4; i++) p[i] = KP[(ty * 4 + i) * 65 + kk];
#pragma unroll
            for (int j = 0; j < 4; j++) vv[j] = Vs[kk * 64 + tx * 4 + j];
#pragma unroll
            for (int i = 0; i < 4; i++)
#pragma unroll
                for (int j = 0; j < 4; j++)
                    acc[i][j] = fmaf(p[i], vv[j], acc[i][j]);
        }
    }

    float* optr = g_ctx + (size_t)(b * S_LEN + q0) * D_MODEL + h * HD;
#pragma unroll
    for (int i = 0; i < 4; i++) {
        const float inv = 1.f / l_i[i];
        float4 o;
        o.x = acc[i][0] * inv;
        o.y = acc[i][1] * inv;
        o.z = acc[i][2] * inv;
        o.w = acc[i][3] * inv;
        *(float4*)(optr + (size_t)(ty * 4 + i) * D_MODEL + tx * 4) = o;
    }
}

// ---------------------------------------------------------------------------
extern "C" void kernel_launch(void* const* d_in, const int* in_sizes, int n_in,
                              void* d_out, int out_size)
{
    const float* x  = (const float*)d_in[0];
    const float* Wq = (const float*)d_in[1];
    const float* bq = (const float*)d_in[2];
    const float* Wk = (const float*)d_in[3];
    const float* bk = (const float*)d_in[4];
    const float* Wv = (const float*)d_in[5];
    const float* bv = (const float*)d_in[6];
    const float* Wo = (const float*)d_in[7];
    const float* bo = (const float*)d_in[8];
    float* out = (float*)d_out;

    float *p_q, *p_k, *p_v, *p_ctx;
    __nv_bfloat16 *p_ah, *p_al, *p_wqh, *p_wql, *p_wkh, *p_wkl,
                  *p_wvh, *p_wvl, *p_woh, *p_wol;
    cudaGetSymbolAddress((void**)&p_q, g_q);
    cudaGetSymbolAddress((void**)&p_k, g_k);
    cudaGetSymbolAddress((void**)&p_v, g_v);
    cudaGetSymbolAddress((void**)&p_ctx, g_ctx);
    cudaGetSymbolAddress((void**)&p_ah, g_ah);
    cudaGetSymbolAddress((void**)&p_al, g_al);
    cudaGetSymbolAddress((void**)&p_wqh, g_wqh);
    cudaGetSymbolAddress((void**)&p_wql, g_wql);
    cudaGetSymbolAddress((void**)&p_wkh, g_wkh);
    cudaGetSymbolAddress((void**)&p_wkl, g_wkl);
    cudaGetSymbolAddress((void**)&p_wvh, g_wvh);
    cudaGetSymbolAddress((void**)&p_wvl, g_wvl);
    cudaGetSymbolAddress((void**)&p_woh, g_woh);
    cudaGetSymbolAddress((void**)&p_wol, g_wol);

    cudaFuncSetAttribute(gemm_mma_kernel,
                         cudaFuncAttributeMaxDynamicSharedMemorySize, SMEM_GEMM);
    cudaFuncSetAttribute(attention_kernel,
                         cudaFuncAttributeMaxDynamicSharedMemorySize, SMEM_ATT);

    // split x into bf16 hi/lo
    split_kernel<<<(NTOK * KTOT / 4 + 255) / 256, 256>>>(x, p_ah, p_al, NTOK * KTOT / 4);
    // transpose+split weights to [N][K]
    transpose_split_kernel<<<dim3(D_MODEL / 32, KTOT / 32), dim3(32, 8)>>>(Wq, p_wqh, p_wql, KTOT, D_MODEL);
    transpose_split_kernel<<<dim3(KV_DIM / 32, KTOT / 32), dim3(32, 8)>>>(Wk, p_wkh, p_wkl, KTOT, KV_DIM);
    transpose_split_kernel<<<dim3(KV_DIM / 32, KTOT / 32), dim3(32, 8)>>>(Wv, p_wvh, p_wvl, KTOT, KV_DIM);
    transpose_split_kernel<<<dim3(D_MODEL / 32, KTOT / 32), dim3(32, 8)>>>(Wo, p_woh, p_wol, KTOT, D_MODEL);

    // projections on tensor cores (mma.sync)
    gemm_mma_kernel<<<dim3(D_MODEL / 128, NTOK / 128), 256, SMEM_GEMM>>>(p_ah, p_al, p_wqh, p_wql, bq, p_q, D_MODEL);
    gemm_mma_kernel<<<dim3(KV_DIM  / 128, NTOK / 128), 256, SMEM_GEMM>>>(p_ah, p_al, p_wkh, p_wkl, bk, p_k, KV_DIM);
    gemm_mma_kernel<<<dim3(KV_DIM  / 128, NTOK / 128), 256, SMEM_GEMM>>>(p_ah, p_al, p_wvh, p_wvl, bv, p_v, KV_DIM);

    attention_kernel<<<dim3(S_LEN / 64, BATCH * HEADS), 256, SMEM_ATT>>>();

    // split ctx (reuse x's split buffers) and O projection
    split_kernel<<<(NTOK * KTOT / 4 + 255) / 256, 256>>>(p_ctx, p_ah, p_al, NTOK * KTOT / 4);
    gemm_mma_kernel<<<dim3(D_MODEL / 128, NTOK / 128), 256, SMEM_GEMM>>>(p_ah, p_al, p_woh, p_wol, bo, out, D_MODEL);
}